// round 6
// baseline (speedup 1.0000x reference)
#include <cuda_runtime.h>
#include <cuda_bf16.h>
#include <math.h>

// Problem dims
#define BSZ   256
#define SIG   64
#define LATD  256
#define ENCH  256
#define DECH  512
#define RHSH  512
#define TSTEPS 200

#define NBLK   128   // persistent ODE grid: 16 clusters x 8 CTAs
#define CLSZ   8     // portable cluster size

// ---------------- scratch (device globals; no allocation) ----------------
__device__ float g_z[TSTEPS * BSZ * LATD];        // pred_z
__device__ float g_h1[BSZ * RHSH];
__device__ float g_h2[BSZ * RHSH];
__device__ float g_kst[3 * BSZ * LATD];           // k1,k2,k3
__device__ float g_x0[3 * BSZ * ENCH];            // enc layer0 out
__device__ float g_x1[2 * BSZ * ENCH];            // enc layer1 out
__device__ float g_hd1[(size_t)TSTEPS * BSZ * DECH];
__device__ float g_hd2[(size_t)TSTEPS * BSZ * DECH];

// ---------------- f32x2 packed-FMA helpers ----------------
__device__ __forceinline__ void fma2(unsigned long long& d,
                                     unsigned long long a,
                                     unsigned long long b)
{
    asm("fma.rn.f32x2 %0, %1, %2, %0;" : "+l"(d) : "l"(a), "l"(b));
}
__device__ __forceinline__ unsigned long long pack2(float x)
{
    unsigned long long r;
    asm("mov.b64 %0, {%1, %1};" : "=l"(r) : "f"(x));
    return r;
}
__device__ __forceinline__ void unpack2(float& lo, float& hi, unsigned long long v)
{
    asm("mov.b64 {%0, %1}, %2;" : "=f"(lo), "=f"(hi) : "l"(v));
}

#define CLUSTER_SYNC() do { \
    asm volatile("barrier.cluster.arrive.aligned;" ::: "memory"); \
    asm volatile("barrier.cluster.wait.aligned;"   ::: "memory"); \
} while (0)

// ---------------- A-tile staging: 16 rows x 256 k-chunk into As[k][16] ----
template<int KDIM, bool HASK>
__device__ __forceinline__ void stage_A(float* __restrict__ As,
                                        const float* __restrict__ Aop,
                                        const float* __restrict__ Kadd,
                                        float c, int m0, int r, int tid)
{
    const int m  = tid & 15;
    const int kq = tid >> 4;   // 0..15
    const float* arow = Aop + (size_t)(m0 + m) * KDIM + r * 256;
    const float* krow = HASK ? (Kadd + (size_t)(m0 + m) * KDIM + r * 256) : nullptr;
#pragma unroll
    for (int it = 0; it < 4; ++it) {
        const int k = (it * 16 + kq) * 4;
        float4 av = __ldcg((const float4*)(arow + k));
        if (HASK) {
            const float4 kv = __ldcg((const float4*)(krow + k));
            av.x += c * kv.x; av.y += c * kv.y;
            av.z += c * kv.z; av.w += c * kv.w;
        }
        As[(k + 0) * 16 + m] = av.x;
        As[(k + 1) * 16 + m] = av.y;
        As[(k + 2) * 16 + m] = av.z;
        As[(k + 3) * 16 + m] = av.w;
    }
}

// ---------------- phases A/B: out[m0:m0+16, n0:n0+64] = tanh(A @ Ws^T + b) --
// Ws: SMEM slice [k][64n]. 256 thr = 4 k-splits x (4 tm x 16 tn), 4m x 4n tiles.
template<int KDIM, bool HASK>
__device__ __forceinline__ void phase_ab(
    const float* __restrict__ Aop, const float* __restrict__ Kadd, float c,
    const float* __restrict__ Ws, const float* __restrict__ biasS,
    float* __restrict__ outbuf, int m0, int n0w,
    float* __restrict__ As, float* __restrict__ red, int tid)
{
    const int ks    = tid >> 6;     // 0..3
    const int inner = tid & 63;
    const int tm    = inner >> 4;   // 0..3
    const int tn    = inner & 15;   // 0..15

    unsigned long long acc2[2][4] = {{0ULL,0ULL,0ULL,0ULL},{0ULL,0ULL,0ULL,0ULL}};

#pragma unroll
    for (int r = 0; r < KDIM / 256; ++r) {
        stage_A<KDIM, HASK>(As, Aop, Kadd, c, m0, r, tid);
        __syncthreads();
        const float* Ag = As + ks * (64 * 16) + tm * 4;
        const float* Wg = Ws + (size_t)(r * 256 + ks * 64) * 64 + tn * 4;
#pragma unroll 8
        for (int i = 0; i < 64; ++i) {
            const ulonglong2 a2 = *(const ulonglong2*)(Ag + i * 16);
            const float4 b4 = *(const float4*)(Wg + i * 64);
            const unsigned long long b0 = pack2(b4.x), b1 = pack2(b4.y),
                                     b2 = pack2(b4.z), b3 = pack2(b4.w);
            fma2(acc2[0][0], a2.x, b0); fma2(acc2[1][0], a2.y, b0);
            fma2(acc2[0][1], a2.x, b1); fma2(acc2[1][1], a2.y, b1);
            fma2(acc2[0][2], a2.x, b2); fma2(acc2[1][2], a2.y, b2);
            fma2(acc2[0][3], a2.x, b3); fma2(acc2[1][3], a2.y, b3);
        }
        __syncthreads();
    }

    // cross-k-split reduction via smem: red[ks][16m][64n]
#pragma unroll
    for (int i = 0; i < 2; ++i)
#pragma unroll
        for (int j = 0; j < 4; ++j) {
            float lo, hi;
            unpack2(lo, hi, acc2[i][j]);
            red[ks * 1024 + (tm * 4 + 2 * i)     * 64 + tn * 4 + j] = lo;
            red[ks * 1024 + (tm * 4 + 2 * i + 1) * 64 + tn * 4 + j] = hi;
        }
    __syncthreads();

#pragma unroll
    for (int it = 0; it < 4; ++it) {
        const int e = it * 256 + tid;
        const int m = e >> 6, n = e & 63;
        const float v = red[m * 64 + n] + red[1024 + m * 64 + n] +
                        red[2048 + m * 64 + n] + red[3072 + m * 64 + n] + biasS[n];
        outbuf[(size_t)(m0 + m) * 512 + n0w + n] = tanhf(v);
    }
}

// ---------------- phase C: out[m0:m0+16, n0c:n0c+32] = A @ W2^T + b2 --------
// W2 streamed from L2 (512KB, shared by all groups). 256 thr = 8 k-splits x
// (4 tm x 8 tn). EPI 0: write k buf.  EPI 2: RK4 combine -> znx.
template<int EPI>
__device__ __forceinline__ void phase_c(
    const float* __restrict__ h2, const float* __restrict__ fw2g,
    const float* __restrict__ b2s, float* __restrict__ outbuf,
    int m0, int n0c, float* __restrict__ As, float* __restrict__ red, int tid,
    const float* __restrict__ zn, const float* __restrict__ K1,
    const float* __restrict__ K2, const float* __restrict__ K3,
    float* __restrict__ znx, float hh)
{
    const int ks    = tid >> 5;     // 0..7
    const int inner = tid & 31;
    const int tm    = inner >> 3;   // 0..3
    const int tn    = inner & 7;    // 0..7

    unsigned long long acc2[2][4] = {{0ULL,0ULL,0ULL,0ULL},{0ULL,0ULL,0ULL,0ULL}};
    const float* w2base = fw2g + (size_t)(n0c + tn * 4) * 512;

#pragma unroll
    for (int r = 0; r < 2; ++r) {
        stage_A<512, false>(As, h2, nullptr, 0.f, m0, r, tid);
        __syncthreads();
#pragma unroll 2
        for (int g4 = 0; g4 < 8; ++g4) {
            const int kglob = r * 256 + ks * 32 + g4 * 4;
            const int kloc  = ks * 32 + g4 * 4;
            float4 b[4];
#pragma unroll
            for (int j = 0; j < 4; ++j)
                b[j] = __ldcg((const float4*)(w2base + (size_t)j * 512 + kglob));
#pragma unroll
            for (int kk = 0; kk < 4; ++kk) {
                const ulonglong2 a2 = *(const ulonglong2*)(As + (kloc + kk) * 16 + tm * 4);
#pragma unroll
                for (int j = 0; j < 4; ++j) {
                    const float bw = ((const float*)&b[j])[kk];
                    const unsigned long long bb = pack2(bw);
                    fma2(acc2[0][j], a2.x, bb);
                    fma2(acc2[1][j], a2.y, bb);
                }
            }
        }
        __syncthreads();
    }

    // reduction: red[ks][16m][32n]
#pragma unroll
    for (int i = 0; i < 2; ++i)
#pragma unroll
        for (int j = 0; j < 4; ++j) {
            float lo, hi;
            unpack2(lo, hi, acc2[i][j]);
            red[ks * 512 + (tm * 4 + 2 * i)     * 32 + tn * 4 + j] = lo;
            red[ks * 512 + (tm * 4 + 2 * i + 1) * 32 + tn * 4 + j] = hi;
        }
    __syncthreads();

#pragma unroll
    for (int it = 0; it < 2; ++it) {
        const int e = it * 256 + tid;
        const int m = e >> 5, n = e & 31;
        float v = b2s[n];
#pragma unroll
        for (int q = 0; q < 8; ++q) v += red[q * 512 + m * 32 + n];
        const size_t idx = (size_t)(m0 + m) * 256 + n0c + n;
        if (EPI == 0) {
            outbuf[idx] = v;
        } else {
            znx[idx] = __ldcg(zn + idx) +
                       hh * (1.f / 6.f) *
                       (__ldcg(K1 + idx) + 2.f * __ldcg(K2 + idx) +
                        2.f * __ldcg(K3 + idx) + v);
        }
    }
}

// ---------------- persistent ODE kernel: clusters of 8, HW barriers ---------
__global__ void __launch_bounds__(256, 1) __cluster_dims__(CLSZ, 1, 1)
ode_kernel(const float* __restrict__ t,
           const float* __restrict__ fw0, const float* __restrict__ fb0,
           const float* __restrict__ fw1, const float* __restrict__ fb1,
           const float* __restrict__ fw2, const float* __restrict__ fb2,
           float* __restrict__ zbuf, float* __restrict__ h1buf,
           float* __restrict__ h2buf, float* __restrict__ kst)
{
    extern __shared__ float smem[];
    float* W0s   = smem;                 // 256k x 64n = 16384 f (64 KB)
    float* W1s   = W0s + 256 * 64;       // 512k x 64n = 32768 f (128 KB)
    float* As    = W1s + 512 * 64;       // 256k x 16m =  4096 f (16 KB)
    float* red   = As  + 256 * 16;       //               4096 f (16 KB)
    float* biasS = red + 4096;           //                160 f
                                         // total 57504 f = 230016 B

    const int tid = threadIdx.x;
    const int c   = blockIdx.x & 7;      // cluster rank = N-slice
    const int grp = blockIdx.x >> 3;     // 0..15 -> 16 batch rows
    const int m0  = grp * 16;
    const int n0w = c * 64;              // phases A,B (N=512)
    const int n0c = c * 32;              // phase C   (N=256)

    // ---- stage weight slices ([k][n]) + biases into SMEM
    for (int e = tid; e < 64 * 256; e += 256) {
        const int n = e >> 8, k = e & 255;
        W0s[k * 64 + n] = fw0[(size_t)(n0w + n) * 256 + k];
    }
    for (int e = tid; e < 64 * 512; e += 256) {
        const int n = e >> 9, k = e & 511;
        W1s[k * 64 + n] = fw1[(size_t)(n0w + n) * 512 + k];
    }
    if (tid < 64)       biasS[tid] = fb0[n0w + tid];
    else if (tid < 128) biasS[tid] = fb1[n0w + tid - 64];
    else if (tid < 160) biasS[tid] = fb2[n0c + tid - 128];
    __syncthreads();

    float* K1 = kst;
    float* K2 = kst + BSZ * LATD;
    float* K3 = kst + 2 * BSZ * LATD;

    for (int n = 0; n < TSTEPS - 1; n++) {
        const float hh = __ldg(&t[n + 1]) - __ldg(&t[n]);
        const float* zn = zbuf + (size_t)n * (BSZ * LATD);
        float* znx      = zbuf + (size_t)(n + 1) * (BSZ * LATD);

        // stage 1: k1 = rhs(z)
        phase_ab<256, false>(zn, nullptr, 0.f, W0s, biasS, h1buf, m0, n0w, As, red, tid);
        CLUSTER_SYNC();
        phase_ab<512, false>(h1buf, nullptr, 0.f, W1s, biasS + 64, h2buf, m0, n0w, As, red, tid);
        CLUSTER_SYNC();
        phase_c<0>(h2buf, fw2, biasS + 128, K1, m0, n0c, As, red, tid, 0, 0, 0, 0, 0, 0.f);
        CLUSTER_SYNC();
        // stage 2: k2 = rhs(z + 0.5h k1)
        phase_ab<256, true>(zn, K1, 0.5f * hh, W0s, biasS, h1buf, m0, n0w, As, red, tid);
        CLUSTER_SYNC();
        phase_ab<512, false>(h1buf, nullptr, 0.f, W1s, biasS + 64, h2buf, m0, n0w, As, red, tid);
        CLUSTER_SYNC();
        phase_c<0>(h2buf, fw2, biasS + 128, K2, m0, n0c, As, red, tid, 0, 0, 0, 0, 0, 0.f);
        CLUSTER_SYNC();
        // stage 3: k3 = rhs(z + 0.5h k2)
        phase_ab<256, true>(zn, K2, 0.5f * hh, W0s, biasS, h1buf, m0, n0w, As, red, tid);
        CLUSTER_SYNC();
        phase_ab<512, false>(h1buf, nullptr, 0.f, W1s, biasS + 64, h2buf, m0, n0w, As, red, tid);
        CLUSTER_SYNC();
        phase_c<0>(h2buf, fw2, biasS + 128, K3, m0, n0c, As, red, tid, 0, 0, 0, 0, 0, 0.f);
        CLUSTER_SYNC();
        // stage 4: k4 = rhs(z + h k3); fused z_{n+1} = z + h/6 (k1+2k2+2k3+k4)
        phase_ab<256, true>(zn, K3, hh, W0s, biasS, h1buf, m0, n0w, As, red, tid);
        CLUSTER_SYNC();
        phase_ab<512, false>(h1buf, nullptr, 0.f, W1s, biasS + 64, h2buf, m0, n0w, As, red, tid);
        CLUSTER_SYNC();
        phase_c<2>(h2buf, fw2, biasS + 128, nullptr, m0, n0c, As, red, tid,
                   zn, K1, K2, K3, znx, hh);
        CLUSTER_SYNC();
    }
}

// ---------------- encoder: fused wcat + im2col gather + GEMM ----------------
template<int G>
__device__ __forceinline__ float gatherA(const float* __restrict__ src, int row, int c)
{
    if (G == 1) {
        const int l = row >> 8, b = row & 255;
        if (c < 192) {
            const int i = c / 3, kk = c - 3 * i, p = l + kk - 1;
            return (p >= 0) ? src[(size_t)b * 65536 + i * 1024 + p] : 0.f;
        }
        return src[(size_t)b * 65536 + (c - 192) * 1024 + l];
    } else if (G == 2) {
        const int l = row >> 8, b = row & 255;
        if (c < 768) {
            const int i = c / 3, kk = c - 3 * i, p = l + kk - 1;
            return (p >= 0) ? src[(size_t)(p * 256 + b) * 256 + i] : 0.f;
        }
        return src[(size_t)(l * 256 + b) * 256 + (c - 768)];
    } else {
        const int b = row;
        if (c < 256)  return src[(size_t)b * 256 + c];
        if (c < 512)  return src[(size_t)(256 + b) * 256 + (c - 256)];
        return src[(size_t)b * 256 + (c - 512)];
    }
}

template<int G>
__device__ __forceinline__ float gatherW(const float* __restrict__ ew,
                                         const float* __restrict__ rw, int o, int c)
{
    if (G == 1) {
        if (c < 192) return ew[o * 192 + c];
        return rw[o * 64 + (c - 192)];
    } else if (G == 2) {
        if (c < 768) return ew[o * 768 + c];
        return rw[o * 256 + (c - 768)];
    } else {
        if (c < 256)  return ew[o * 768 + c * 3 + 1];
        if (c < 512)  return ew[o * 768 + (c - 256) * 3 + 2];
        return rw[o * 256 + (c - 512)];
    }
}

template<int G, int TANH>
__launch_bounds__(256)
__global__ void enc_gemm(const float* __restrict__ Asrc,
                         const float* __restrict__ ew, const float* __restrict__ rw,
                         const float* __restrict__ eb, const float* __restrict__ rb,
                         float* __restrict__ C, int K)
{
    __shared__ float As[32][34];
    __shared__ float Bs[32][34];

    const int tid = threadIdx.x;
    const int tx  = tid & 15;
    const int ty  = tid >> 4;
    const int m0  = blockIdx.y * 32;
    const int n0  = blockIdx.x * 32;

    const int ar = tid >> 3;
    const int ak = (tid & 7) * 4;

    float acc[2][2] = {{0.f, 0.f}, {0.f, 0.f}};

    for (int k0 = 0; k0 < K; k0 += 32) {
#pragma unroll
        for (int j = 0; j < 4; j++) {
            As[ak + j][ar] = gatherA<G>(Asrc, m0 + ar, k0 + ak + j);
            Bs[ak + j][ar] = gatherW<G>(ew, rw, n0 + ar, k0 + ak + j);
        }
        __syncthreads();
#pragma unroll
        for (int k = 0; k < 32; k++) {
            const float a0 = As[k][ty * 2], a1 = As[k][ty * 2 + 1];
            const float b0 = Bs[k][tx * 2], b1 = Bs[k][tx * 2 + 1];
            acc[0][0] = fmaf(a0, b0, acc[0][0]);
            acc[0][1] = fmaf(a0, b1, acc[0][1]);
            acc[1][0] = fmaf(a1, b0, acc[1][0]);
            acc[1][1] = fmaf(a1, b1, acc[1][1]);
        }
        __syncthreads();
    }

#pragma unroll
    for (int i = 0; i < 2; i++) {
        const int m = m0 + ty * 2 + i;
#pragma unroll
        for (int j = 0; j < 2; j++) {
            const int n = n0 + tx * 2 + j;
            float v = acc[i][j] + eb[n] + rb[n];
            if (TANH) v = tanhf(v);
            C[(size_t)m * 256 + n] = v;
        }
    }
}

// ---------------- decoder GEMM: 64x64x16 tile, f32x2 inner ----------------
template<int EPI>
__launch_bounds__(256)
__global__ void dec_gemm(const float* __restrict__ A,
                         const float* __restrict__ W,
                         const float* __restrict__ bias,
                         float* __restrict__ C,
                         int M, int N, int K)
{
    __shared__ float As[16][68];
    __shared__ float Bs[16][68];

    const int tid = threadIdx.x;
    const int tx  = tid & 15;
    const int ty  = tid >> 4;
    const int m0  = blockIdx.y * 64;
    const int n0  = blockIdx.x * 64;

    const int ar = tid >> 2;
    const int ak = (tid & 3) * 4;

    unsigned long long acc2[2][4];
#pragma unroll
    for (int i = 0; i < 2; i++)
#pragma unroll
        for (int j = 0; j < 4; j++) acc2[i][j] = 0ULL;

    const float* Aptr = A + (size_t)(m0 + ar) * K + ak;
    const float* Wptr = W + (size_t)(n0 + ar) * K + ak;

    for (int k0 = 0; k0 < K; k0 += 16) {
        const float4 av = *(const float4*)(Aptr + k0);
        const float4 bv = *(const float4*)(Wptr + k0);
        As[ak + 0][ar] = av.x; As[ak + 1][ar] = av.y;
        As[ak + 2][ar] = av.z; As[ak + 3][ar] = av.w;
        Bs[ak + 0][ar] = bv.x; Bs[ak + 1][ar] = bv.y;
        Bs[ak + 2][ar] = bv.z; Bs[ak + 3][ar] = bv.w;
        __syncthreads();
#pragma unroll
        for (int k = 0; k < 16; k++) {
            const ulonglong2 a2 = *(const ulonglong2*)(&As[k][ty * 4]);
            const float4 b4 = *(const float4*)(&Bs[k][tx * 4]);
            unsigned long long bb[4];
            bb[0] = pack2(b4.x); bb[1] = pack2(b4.y);
            bb[2] = pack2(b4.z); bb[3] = pack2(b4.w);
#pragma unroll
            for (int j = 0; j < 4; j++) {
                fma2(acc2[0][j], a2.x, bb[j]);
                fma2(acc2[1][j], a2.y, bb[j]);
            }
        }
        __syncthreads();
    }

#pragma unroll
    for (int i = 0; i < 2; i++) {
#pragma unroll
        for (int j = 0; j < 4; j++) {
            float lo, hi;
            unpack2(lo, hi, acc2[i][j]);
            const int n = n0 + tx * 4 + j;
            const float bval = bias[n];
#pragma unroll
            for (int half = 0; half < 2; half++) {
                const int m = m0 + ty * 4 + 2 * i + half;
                float v = (half == 0 ? lo : hi) + bval;
                if (EPI == 1) v = tanhf(v);
                if (EPI == 3) {
                    const int tt = m >> 8;
                    const int bb2 = m & 255;
                    C[(size_t)bb2 * (SIG * TSTEPS) + (size_t)n * TSTEPS + tt] = v;
                } else {
                    C[(size_t)m * N + n] = v;
                }
            }
        }
    }
}

extern "C" void kernel_launch(void* const* d_in, const int* in_sizes, int n_in,
                              void* d_out, int out_size)
{
    const float* y   = (const float*)d_in[0];
    const float* t   = (const float*)d_in[1];
    const float* ew0 = (const float*)d_in[2];
    const float* eb0 = (const float*)d_in[3];
    const float* rw0 = (const float*)d_in[4];
    const float* rb0 = (const float*)d_in[5];
    const float* ew1 = (const float*)d_in[6];
    const float* eb1 = (const float*)d_in[7];
    const float* rw1 = (const float*)d_in[8];
    const float* rb1 = (const float*)d_in[9];
    const float* ew2 = (const float*)d_in[10];
    const float* eb2 = (const float*)d_in[11];
    const float* rw2 = (const float*)d_in[12];
    const float* rb2 = (const float*)d_in[13];
    const float* fw0 = (const float*)d_in[14];
    const float* fb0 = (const float*)d_in[15];
    const float* fw1 = (const float*)d_in[16];
    const float* fb1 = (const float*)d_in[17];
    const float* fw2 = (const float*)d_in[18];
    const float* fb2 = (const float*)d_in[19];
    const float* dw0 = (const float*)d_in[20];
    const float* db0 = (const float*)d_in[21];
    const float* dw1 = (const float*)d_in[22];
    const float* db1 = (const float*)d_in[23];
    const float* dw2 = (const float*)d_in[24];
    const float* db2 = (const float*)d_in[25];
    float* out = (float*)d_out;

    float *zbuf, *h1, *h2, *kst, *x0, *x1, *hd1, *hd2;
    cudaGetSymbolAddress((void**)&zbuf, g_z);
    cudaGetSymbolAddress((void**)&h1,  g_h1);
    cudaGetSymbolAddress((void**)&h2,  g_h2);
    cudaGetSymbolAddress((void**)&kst, g_kst);
    cudaGetSymbolAddress((void**)&x0,  g_x0);
    cudaGetSymbolAddress((void**)&x1,  g_x1);
    cudaGetSymbolAddress((void**)&hd1, g_hd1);
    cudaGetSymbolAddress((void**)&hd2, g_hd2);

    // ---------- encoder: 3 fused gather-GEMMs ----------
    { dim3 g(8, 24); enc_gemm<1, 1><<<g, 256>>>(y,  ew0, rw0, eb0, rb0, x0, 256);  }
    { dim3 g(8, 16); enc_gemm<2, 1><<<g, 256>>>(x0, ew1, rw1, eb1, rb1, x1, 1024); }
    { dim3 g(8, 8);  enc_gemm<3, 0><<<g, 256>>>(x1, ew2, rw2, eb2, rb2, zbuf, 768);}

    // ---------- RK4 ODE: persistent kernel, 16 clusters of 8 CTAs ----------
    const int smem_bytes = (256 * 64 + 512 * 64 + 256 * 16 + 4096 + 160) * 4;
    cudaFuncSetAttribute(ode_kernel, cudaFuncAttributeMaxDynamicSharedMemorySize,
                         smem_bytes);
    ode_kernel<<<NBLK, 256, smem_bytes>>>(t, fw0, fb0, fw1, fb1, fw2, fb2,
                                          zbuf, h1, h2, kst);

    // ---------- decoder over all 200 states ----------
    { dim3 g(DECH / 64, TSTEPS * BSZ / 64); dec_gemm<1><<<g, 256>>>(zbuf, dw0, db0, hd1, TSTEPS * BSZ, DECH, LATD); }
    { dim3 g(DECH / 64, TSTEPS * BSZ / 64); dec_gemm<1><<<g, 256>>>(hd1,  dw1, db1, hd2, TSTEPS * BSZ, DECH, DECH); }
    { dim3 g(SIG  / 64, TSTEPS * BSZ / 64); dec_gemm<3><<<g, 256>>>(hd2,  dw2, db2, out, TSTEPS * BSZ, SIG,  DECH); }
}

// round 7
// speedup vs baseline: 2.0309x; 2.0309x over previous
#include <cuda_runtime.h>
#include <cuda_bf16.h>
#include <math.h>

// Problem dims
#define BSZ   256
#define SIG   64
#define LATD  256
#define ENCH  256
#define DECH  512
#define RHSH  512
#define TSTEPS 200

#define NBLK   128   // persistent ODE grid: 8 groups x 16 CTAs
#define GRPSZ  16
#define NGRP   8

// ---------------- scratch (device globals; no allocation) ----------------
__device__ float g_z[TSTEPS * BSZ * LATD];        // pred_z
__device__ float g_h1[BSZ * RHSH];
__device__ float g_h2[BSZ * RHSH];
__device__ float g_s[BSZ * RHSH];                 // RK4 combined h2 sum
__device__ float g_G[RHSH * RHSH];                // G = fw0 @ fw2  (512x512)
__device__ float g_g0[RHSH];                      // g0 = fw0 @ fb2
__device__ float g_x0[3 * BSZ * ENCH];
__device__ float g_x1[2 * BSZ * ENCH];
__device__ float g_hd1[(size_t)TSTEPS * BSZ * DECH];
__device__ float g_hd2[(size_t)TSTEPS * BSZ * DECH];

// per-group barrier state (one L2 line per group)
__device__ unsigned g_arr[NGRP * 32];
__device__ unsigned g_gen[NGRP * 32];

// ---------------- f32x2 packed-FMA helpers ----------------
__device__ __forceinline__ void fma2(unsigned long long& d,
                                     unsigned long long a,
                                     unsigned long long b)
{
    asm("fma.rn.f32x2 %0, %1, %2, %0;" : "+l"(d) : "l"(a), "l"(b));
}
__device__ __forceinline__ unsigned long long pack2(float x)
{
    unsigned long long r;
    asm("mov.b64 %0, {%1, %1};" : "=l"(r) : "f"(x));
    return r;
}
__device__ __forceinline__ void unpack2(float& lo, float& hi, unsigned long long v)
{
    asm("mov.b64 {%0, %1}, %2;" : "=f"(lo), "=f"(hi) : "l"(v));
}

// ---------------- group barrier (16 CTAs) ----------------
__device__ __forceinline__ void gsync(unsigned* arr, unsigned* gen, unsigned& lg)
{
    __syncthreads();
    if (threadIdx.x == 0) {
        unsigned ticket;
        asm volatile("atom.acq_rel.gpu.add.u32 %0, [%1], 1;"
                     : "=r"(ticket) : "l"(arr) : "memory");
        const unsigned target = lg + 1;
        if ((ticket & (GRPSZ - 1)) == GRPSZ - 1) {
            asm volatile("st.release.gpu.u32 [%0], %1;"
                         :: "l"(gen), "r"(target) : "memory");
        } else {
            unsigned g;
            do {
                asm volatile("ld.acquire.gpu.u32 %0, [%1];"
                             : "=r"(g) : "l"(gen) : "memory");
            } while ((int)(g - target) < 0);
        }
        lg = target;
    }
    __syncthreads();
}

// ---------------- A staging: 32 rows x 256-k chunk (row stride 512) --------
__device__ __forceinline__ void stageA(float* __restrict__ As,
                                       const float* __restrict__ Abuf,
                                       int m0, int r, int tid)
{
    const int m  = tid & 31;
    const int kq = tid >> 5;
    const float* row = Abuf + (size_t)(m0 + m) * 512 + r * 256;
#pragma unroll
    for (int it = 0; it < 8; ++it) {
        const int k = (it * 8 + kq) * 4;
        const float4 v = __ldcg((const float4*)(row + k));
        As[(k + 0) * 32 + m] = v.x;
        As[(k + 1) * 32 + m] = v.y;
        As[(k + 2) * 32 + m] = v.z;
        As[(k + 3) * 32 + m] = v.w;
    }
}

// ---------------- core GEMM: red = A(32x512) @ Ws(512x32 [k][n]) ----------
// 256 thr = 4 k-splits x (8tm x 8tn), thread tile 4m x 4n, f32x2 accum.
// Leaves partials in red[4][32][32]; caller sums red[q] + epilogue.
__device__ __forceinline__ void gemm32(const float* __restrict__ Abuf,
                                       const float* __restrict__ Ws,
                                       float* __restrict__ As,
                                       float* __restrict__ red,
                                       int m0, int tid)
{
    const int ks = tid >> 6, inner = tid & 63;
    const int tm = inner >> 3, tn = inner & 7;
    unsigned long long acc[2][4] = {{0ULL,0ULL,0ULL,0ULL},{0ULL,0ULL,0ULL,0ULL}};

#pragma unroll
    for (int r = 0; r < 2; ++r) {
        stageA(As, Abuf, m0, r, tid);
        __syncthreads();
        const float* Ag = As + ks * 64 * 32 + tm * 4;
        const float* Wg = Ws + (size_t)(r * 256 + ks * 64) * 32 + tn * 4;
#pragma unroll 8
        for (int i = 0; i < 64; ++i) {
            const ulonglong2 a2 = *(const ulonglong2*)(Ag + i * 32);
            const float4 b4 = *(const float4*)(Wg + i * 32);
            const unsigned long long b0 = pack2(b4.x), b1 = pack2(b4.y),
                                     b2 = pack2(b4.z), b3 = pack2(b4.w);
            fma2(acc[0][0], a2.x, b0); fma2(acc[1][0], a2.y, b0);
            fma2(acc[0][1], a2.x, b1); fma2(acc[1][1], a2.y, b1);
            fma2(acc[0][2], a2.x, b2); fma2(acc[1][2], a2.y, b2);
            fma2(acc[0][3], a2.x, b3); fma2(acc[1][3], a2.y, b3);
        }
        __syncthreads();
    }
#pragma unroll
    for (int i = 0; i < 2; ++i)
#pragma unroll
        for (int j = 0; j < 4; ++j) {
            float lo, hi;
            unpack2(lo, hi, acc[i][j]);
            red[ks * 1024 + (tm * 4 + 2 * i)     * 32 + tn * 4 + j] = lo;
            red[ks * 1024 + (tm * 4 + 2 * i + 1) * 32 + tn * 4 + j] = hi;
        }
    __syncthreads();
}

__device__ __forceinline__ float red4(const float* __restrict__ red, int m, int n)
{
    return red[m * 32 + n] + red[1024 + m * 32 + n] +
           red[2048 + m * 32 + n] + red[3072 + m * 32 + n];
}

// ---------------- z GEMM: red = s(32x512) @ W2s(512x16 [k][n]) -------------
// 256 thr = 8 k-splits x (8tm x 4tn), thread tile 4m x 4n.
__device__ __forceinline__ void gemmZ(const float* __restrict__ Abuf,
                                      const float* __restrict__ Ws,
                                      float* __restrict__ As,
                                      float* __restrict__ red,
                                      int m0, int tid)
{
    const int ks = tid >> 5, inner = tid & 31;
    const int tm = inner >> 2, tn = inner & 3;
    unsigned long long acc[2][4] = {{0ULL,0ULL,0ULL,0ULL},{0ULL,0ULL,0ULL,0ULL}};

#pragma unroll
    for (int r = 0; r < 2; ++r) {
        stageA(As, Abuf, m0, r, tid);
        __syncthreads();
        const float* Ag = As + ks * 32 * 32 + tm * 4;
        const float* Wg = Ws + (size_t)(r * 256 + ks * 32) * 16 + tn * 4;
#pragma unroll 8
        for (int i = 0; i < 32; ++i) {
            const ulonglong2 a2 = *(const ulonglong2*)(Ag + i * 32);
            const float4 b4 = *(const float4*)(Wg + i * 16);
            const unsigned long long b0 = pack2(b4.x), b1 = pack2(b4.y),
                                     b2 = pack2(b4.z), b3 = pack2(b4.w);
            fma2(acc[0][0], a2.x, b0); fma2(acc[1][0], a2.y, b0);
            fma2(acc[0][1], a2.x, b1); fma2(acc[1][1], a2.y, b1);
            fma2(acc[0][2], a2.x, b2); fma2(acc[1][2], a2.y, b2);
            fma2(acc[0][3], a2.x, b3); fma2(acc[1][3], a2.y, b3);
        }
        __syncthreads();
    }
#pragma unroll
    for (int i = 0; i < 2; ++i)
#pragma unroll
        for (int j = 0; j < 4; ++j) {
            float lo, hi;
            unpack2(lo, hi, acc[i][j]);
            red[ks * 512 + (tm * 4 + 2 * i)     * 16 + tn * 4 + j] = lo;
            red[ks * 512 + (tm * 4 + 2 * i + 1) * 16 + tn * 4 + j] = hi;
        }
    __syncthreads();
}

// ---------------- persistent ODE kernel (w-space reformulation) ------------
__global__ void __launch_bounds__(256, 1) ode_kernel(
    const float* __restrict__ t,
    const float* __restrict__ fw0, const float* __restrict__ fb0,
    const float* __restrict__ fw1, const float* __restrict__ fb1,
    const float* __restrict__ fw2, const float* __restrict__ fb2,
    const float* __restrict__ Gm,  const float* __restrict__ g0,
    float* __restrict__ zbuf, float* __restrict__ h1buf,
    float* __restrict__ h2buf, float* __restrict__ sbuf)
{
    extern __shared__ float smem[];
    float* W1s = smem;                 // 512k x 32n = 16384 f (64 KB)
    float* Gs  = W1s + 16384;          // 512k x 32n = 16384 f (64 KB)
    float* W2s = Gs  + 16384;          // 512k x 16n =  8192 f (32 KB)
    float* As  = W2s + 8192;           // 256k x 32m =  8192 f (32 KB)
    float* red = As  + 8192;           //               4096 f (16 KB)
    float* bS  = red + 4096;           // b1(32) | g0(32) | b2(16) = 80 f

    const int tid = threadIdx.x;
    const int c   = blockIdx.x & 15;   // N-slice 0..15
    const int grp = blockIdx.x >> 4;   // batch group 0..7
    const int m0  = grp * 32;
    const int n0  = c * 32;            // 512-dim slice start
    const int nz0 = c * 16;            // 256-dim slice start

    // ---- stage weight slices ([k][n]) + biases
    for (int e = tid; e < 32 * 512; e += 256) {
        const int n = e >> 9, k = e & 511;
        W1s[k * 32 + n] = fw1[(size_t)(n0 + n) * 512 + k];
        Gs [k * 32 + n] = Gm [(size_t)(n0 + n) * 512 + k];
    }
    for (int e = tid; e < 16 * 512; e += 256) {
        const int n = e >> 9, k = e & 511;
        W2s[k * 16 + n] = fw2[(size_t)(nz0 + n) * 512 + k];
    }
    if (tid < 32)       bS[tid] = fb1[n0 + tid];
    else if (tid < 64)  bS[tid] = g0[n0 + tid - 32];
    else if (tid < 80)  bS[tid] = fb2[nz0 + tid - 64];
    __syncthreads();

    // ---- per-thread persistent registers (element it <-> row (tid>>5)+8it, col tid&31)
    const int mr = tid >> 5;
    const int nn = tid & 31;
    float w[4], u[4] = {0.f, 0.f, 0.f, 0.f}, s[4] = {0.f, 0.f, 0.f, 0.f};

    // ---- init w = W0 @ z0 + b0 (one-time; z0 = zbuf[0])
    {
        const int m  = tid & 31;
        const int kq = tid >> 5;
        const float* row = zbuf + (size_t)(m0 + m) * 256;
#pragma unroll
        for (int it = 0; it < 8; ++it) {
            const int k = (it * 8 + kq) * 4;
            const float4 v = __ldcg((const float4*)(row + k));
            As[(k + 0) * 32 + m] = v.x; As[(k + 1) * 32 + m] = v.y;
            As[(k + 2) * 32 + m] = v.z; As[(k + 3) * 32 + m] = v.w;
        }
        __syncthreads();
        const float b0v = fb0[n0 + nn];
        float wa[4] = {b0v, b0v, b0v, b0v};
        const float* w0row = fw0 + (size_t)(n0 + nn) * 256;
        for (int l = 0; l < 256; l += 4) {
            const float4 wv = __ldcg((const float4*)(w0row + l));
#pragma unroll
            for (int j = 0; j < 4; ++j) {
                const float wj = (&wv.x)[j];
#pragma unroll
                for (int i = 0; i < 4; ++i)
                    wa[i] = fmaf(As[(l + j) * 32 + mr + 8 * i], wj, wa[i]);
            }
        }
#pragma unroll
        for (int i = 0; i < 4; ++i) w[i] = wa[i];
        __syncthreads();
    }

    unsigned* arr = &g_arr[grp * 32];
    unsigned* gen = &g_gen[grp * 32];
    unsigned lg = 0;
    if (tid == 0)
        asm volatile("ld.acquire.gpu.u32 %0, [%1];" : "=r"(lg) : "l"(gen) : "memory");

    for (int n = 0; n < TSTEPS - 1; ++n) {
        const float hh = __ldg(&t[n + 1]) - __ldg(&t[n]);
        const float h6 = hh * (1.f / 6.f);
        const float* zn = zbuf + (size_t)n * (BSZ * LATD);
        float* znx      = zbuf + (size_t)(n + 1) * (BSZ * LATD);

#pragma unroll 1
        for (int st = 0; st < 4; ++st) {
            const float cc = (st == 0) ? 0.f : ((st == 3) ? hh : 0.5f * hh);
            const float sw = (st == 1 || st == 2) ? 2.f : 1.f;

            if (st > 0) {               // u = G @ h2 + g0
                gemm32(h2buf, Gs, As, red, m0, tid);
#pragma unroll
                for (int it = 0; it < 4; ++it)
                    u[it] = red4(red, mr + 8 * it, nn) + bS[32 + nn];
            }
            // h1 = tanh(w + c*u), store slice
#pragma unroll
            for (int it = 0; it < 4; ++it)
                h1buf[(size_t)(m0 + mr + 8 * it) * 512 + n0 + nn] =
                    tanhf(fmaf(cc, u[it], w[it]));
            gsync(arr, gen, lg);

            // h2 = tanh(W1 @ h1 + b1); s += sw*h2
            gemm32(h1buf, W1s, As, red, m0, tid);
#pragma unroll
            for (int it = 0; it < 4; ++it) {
                const int m = mr + 8 * it;
                float v = red4(red, m, nn) + bS[nn];
                v = tanhf(v);
                s[it] = fmaf(sw, v, s[it]);
                if (st < 3) h2buf[(size_t)(m0 + m) * 512 + n0 + nn] = v;
                else        sbuf [(size_t)(m0 + m) * 512 + n0 + nn] = s[it];
            }
            gsync(arr, gen, lg);
        }

        // ---- end of step: w += (h/6) G s + h g0 ; z_{n+1} = z_n + (h/6) W2 s + h b2
        gemm32(sbuf, Gs, As, red, m0, tid);
#pragma unroll
        for (int it = 0; it < 4; ++it)
            w[it] += h6 * red4(red, mr + 8 * it, nn) + hh * bS[32 + nn];

        gemmZ(sbuf, W2s, As, red, m0, tid);
#pragma unroll
        for (int it = 0; it < 2; ++it) {
            const int e = it * 256 + tid;
            const int m = e >> 4, nz = e & 15;
            float v = 0.f;
#pragma unroll
            for (int q = 0; q < 8; ++q) v += red[q * 512 + m * 16 + nz];
            const size_t idx = (size_t)(m0 + m) * 256 + nz0 + nz;
            znx[idx] = __ldcg(zn + idx) + h6 * v + hh * bS[64 + nz];
        }
#pragma unroll
        for (int i = 0; i < 4; ++i) s[i] = 0.f;
    }
}

// ---------------- G = fw0 @ fw2 precompute (NN GEMM 512x512x256) -----------
__launch_bounds__(256)
__global__ void gemmG_kernel(const float* __restrict__ fw0,
                             const float* __restrict__ fw2,
                             float* __restrict__ G)
{
    __shared__ float As[16][68];
    __shared__ float Bs[16][68];
    const int tid = threadIdx.x;
    const int tx = tid & 15, ty = tid >> 4;
    const int m0 = blockIdx.y * 64, n0 = blockIdx.x * 64;

    float acc[4][4] = {};
    for (int k0 = 0; k0 < 256; k0 += 16) {
        {
            const int ar = tid >> 2, ak = (tid & 3) * 4;
            const float4 av = *(const float4*)(fw0 + (size_t)(m0 + ar) * 256 + k0 + ak);
            As[ak + 0][ar] = av.x; As[ak + 1][ar] = av.y;
            As[ak + 2][ar] = av.z; As[ak + 3][ar] = av.w;
            const int kk = tid >> 4, bn = (tid & 15) * 4;
            const float4 bv = *(const float4*)(fw2 + (size_t)(k0 + kk) * 512 + n0 + bn);
            *(float4*)&Bs[kk][bn] = bv;
        }
        __syncthreads();
#pragma unroll
        for (int k = 0; k < 16; ++k) {
            float a[4], b[4];
#pragma unroll
            for (int i = 0; i < 4; ++i) a[i] = As[k][ty * 4 + i];
#pragma unroll
            for (int j = 0; j < 4; ++j) b[j] = Bs[k][tx * 4 + j];
#pragma unroll
            for (int i = 0; i < 4; ++i)
#pragma unroll
                for (int j = 0; j < 4; ++j) acc[i][j] = fmaf(a[i], b[j], acc[i][j]);
        }
        __syncthreads();
    }
#pragma unroll
    for (int i = 0; i < 4; ++i)
#pragma unroll
        for (int j = 0; j < 4; ++j)
            G[(size_t)(m0 + ty * 4 + i) * 512 + n0 + tx * 4 + j] = acc[i][j];
}

__global__ void g0_kernel(const float* __restrict__ fw0,
                          const float* __restrict__ fb2,
                          float* __restrict__ g0)
{
    const int n = blockIdx.x * 256 + threadIdx.x;
    float acc = 0.f;
    for (int l = 0; l < 256; ++l)
        acc = fmaf(fw0[(size_t)n * 256 + l], fb2[l], acc);
    g0[n] = acc;
}

// ---------------- encoder: fused wcat + im2col gather + GEMM ----------------
template<int G>
__device__ __forceinline__ float gatherA(const float* __restrict__ src, int row, int c)
{
    if (G == 1) {
        const int l = row >> 8, b = row & 255;
        if (c < 192) {
            const int i = c / 3, kk = c - 3 * i, p = l + kk - 1;
            return (p >= 0) ? src[(size_t)b * 65536 + i * 1024 + p] : 0.f;
        }
        return src[(size_t)b * 65536 + (c - 192) * 1024 + l];
    } else if (G == 2) {
        const int l = row >> 8, b = row & 255;
        if (c < 768) {
            const int i = c / 3, kk = c - 3 * i, p = l + kk - 1;
            return (p >= 0) ? src[(size_t)(p * 256 + b) * 256 + i] : 0.f;
        }
        return src[(size_t)(l * 256 + b) * 256 + (c - 768)];
    } else {
        const int b = row;
        if (c < 256)  return src[(size_t)b * 256 + c];
        if (c < 512)  return src[(size_t)(256 + b) * 256 + (c - 256)];
        return src[(size_t)b * 256 + (c - 512)];
    }
}

template<int G>
__device__ __forceinline__ float gatherW(const float* __restrict__ ew,
                                         const float* __restrict__ rw, int o, int c)
{
    if (G == 1) {
        if (c < 192) return ew[o * 192 + c];
        return rw[o * 64 + (c - 192)];
    } else if (G == 2) {
        if (c < 768) return ew[o * 768 + c];
        return rw[o * 256 + (c - 768)];
    } else {
        if (c < 256)  return ew[o * 768 + c * 3 + 1];
        if (c < 512)  return ew[o * 768 + (c - 256) * 3 + 2];
        return rw[o * 256 + (c - 512)];
    }
}

template<int G, int TANH>
__launch_bounds__(256)
__global__ void enc_gemm(const float* __restrict__ Asrc,
                         const float* __restrict__ ew, const float* __restrict__ rw,
                         const float* __restrict__ eb, const float* __restrict__ rb,
                         float* __restrict__ C, int K)
{
    __shared__ float As[32][34];
    __shared__ float Bs[32][34];

    const int tid = threadIdx.x;
    const int tx  = tid & 15;
    const int ty  = tid >> 4;
    const int m0  = blockIdx.y * 32;
    const int n0  = blockIdx.x * 32;

    const int ar = tid >> 3;
    const int ak = (tid & 7) * 4;

    float acc[2][2] = {{0.f, 0.f}, {0.f, 0.f}};

    for (int k0 = 0; k0 < K; k0 += 32) {
#pragma unroll
        for (int j = 0; j < 4; j++) {
            As[ak + j][ar] = gatherA<G>(Asrc, m0 + ar, k0 + ak + j);
            Bs[ak + j][ar] = gatherW<G>(ew, rw, n0 + ar, k0 + ak + j);
        }
        __syncthreads();
#pragma unroll
        for (int k = 0; k < 32; k++) {
            const float a0 = As[k][ty * 2], a1 = As[k][ty * 2 + 1];
            const float b0 = Bs[k][tx * 2], b1 = Bs[k][tx * 2 + 1];
            acc[0][0] = fmaf(a0, b0, acc[0][0]);
            acc[0][1] = fmaf(a0, b1, acc[0][1]);
            acc[1][0] = fmaf(a1, b0, acc[1][0]);
            acc[1][1] = fmaf(a1, b1, acc[1][1]);
        }
        __syncthreads();
    }

#pragma unroll
    for (int i = 0; i < 2; i++) {
        const int m = m0 + ty * 2 + i;
#pragma unroll
        for (int j = 0; j < 2; j++) {
            const int n = n0 + tx * 2 + j;
            float v = acc[i][j] + eb[n] + rb[n];
            if (TANH) v = tanhf(v);
            C[(size_t)m * 256 + n] = v;
        }
    }
}

// ---------------- decoder GEMM: 64x64x16 tile, f32x2 inner ----------------
template<int EPI>
__launch_bounds__(256)
__global__ void dec_gemm(const float* __restrict__ A,
                         const float* __restrict__ W,
                         const float* __restrict__ bias,
                         float* __restrict__ C,
                         int M, int N, int K)
{
    __shared__ float As[16][68];
    __shared__ float Bs[16][68];

    const int tid = threadIdx.x;
    const int tx  = tid & 15;
    const int ty  = tid >> 4;
    const int m0  = blockIdx.y * 64;
    const int n0  = blockIdx.x * 64;

    const int ar = tid >> 2;
    const int ak = (tid & 3) * 4;

    unsigned long long acc2[2][4];
#pragma unroll
    for (int i = 0; i < 2; i++)
#pragma unroll
        for (int j = 0; j < 4; j++) acc2[i][j] = 0ULL;

    const float* Aptr = A + (size_t)(m0 + ar) * K + ak;
    const float* Wptr = W + (size_t)(n0 + ar) * K + ak;

    for (int k0 = 0; k0 < K; k0 += 16) {
        const float4 av = *(const float4*)(Aptr + k0);
        const float4 bv = *(const float4*)(Wptr + k0);
        As[ak + 0][ar] = av.x; As[ak + 1][ar] = av.y;
        As[ak + 2][ar] = av.z; As[ak + 3][ar] = av.w;
        Bs[ak + 0][ar] = bv.x; Bs[ak + 1][ar] = bv.y;
        Bs[ak + 2][ar] = bv.z; Bs[ak + 3][ar] = bv.w;
        __syncthreads();
#pragma unroll
        for (int k = 0; k < 16; k++) {
            const ulonglong2 a2 = *(const ulonglong2*)(&As[k][ty * 4]);
            const float4 b4 = *(const float4*)(&Bs[k][tx * 4]);
            unsigned long long bb[4];
            bb[0] = pack2(b4.x); bb[1] = pack2(b4.y);
            bb[2] = pack2(b4.z); bb[3] = pack2(b4.w);
#pragma unroll
            for (int j = 0; j < 4; j++) {
                fma2(acc2[0][j], a2.x, bb[j]);
                fma2(acc2[1][j], a2.y, bb[j]);
            }
        }
        __syncthreads();
    }

#pragma unroll
    for (int i = 0; i < 2; i++) {
#pragma unroll
        for (int j = 0; j < 4; j++) {
            float lo, hi;
            unpack2(lo, hi, acc2[i][j]);
            const int n = n0 + tx * 4 + j;
            const float bval = bias[n];
#pragma unroll
            for (int half = 0; half < 2; half++) {
                const int m = m0 + ty * 4 + 2 * i + half;
                float v = (half == 0 ? lo : hi) + bval;
                if (EPI == 1) v = tanhf(v);
                if (EPI == 3) {
                    const int tt = m >> 8;
                    const int bb2 = m & 255;
                    C[(size_t)bb2 * (SIG * TSTEPS) + (size_t)n * TSTEPS + tt] = v;
                } else {
                    C[(size_t)m * N + n] = v;
                }
            }
        }
    }
}

extern "C" void kernel_launch(void* const* d_in, const int* in_sizes, int n_in,
                              void* d_out, int out_size)
{
    const float* y   = (const float*)d_in[0];
    const float* t   = (const float*)d_in[1];
    const float* ew0 = (const float*)d_in[2];
    const float* eb0 = (const float*)d_in[3];
    const float* rw0 = (const float*)d_in[4];
    const float* rb0 = (const float*)d_in[5];
    const float* ew1 = (const float*)d_in[6];
    const float* eb1 = (const float*)d_in[7];
    const float* rw1 = (const float*)d_in[8];
    const float* rb1 = (const float*)d_in[9];
    const float* ew2 = (const float*)d_in[10];
    const float* eb2 = (const float*)d_in[11];
    const float* rw2 = (const float*)d_in[12];
    const float* rb2 = (const float*)d_in[13];
    const float* fw0 = (const float*)d_in[14];
    const float* fb0 = (const float*)d_in[15];
    const float* fw1 = (const float*)d_in[16];
    const float* fb1 = (const float*)d_in[17];
    const float* fw2 = (const float*)d_in[18];
    const float* fb2 = (const float*)d_in[19];
    const float* dw0 = (const float*)d_in[20];
    const float* db0 = (const float*)d_in[21];
    const float* dw1 = (const float*)d_in[22];
    const float* db1 = (const float*)d_in[23];
    const float* dw2 = (const float*)d_in[24];
    const float* db2 = (const float*)d_in[25];
    float* out = (float*)d_out;

    float *zbuf, *h1, *h2, *sbuf, *Gm, *g0, *x0, *x1, *hd1, *hd2;
    cudaGetSymbolAddress((void**)&zbuf, g_z);
    cudaGetSymbolAddress((void**)&h1,   g_h1);
    cudaGetSymbolAddress((void**)&h2,   g_h2);
    cudaGetSymbolAddress((void**)&sbuf, g_s);
    cudaGetSymbolAddress((void**)&Gm,   g_G);
    cudaGetSymbolAddress((void**)&g0,   g_g0);
    cudaGetSymbolAddress((void**)&x0,   g_x0);
    cudaGetSymbolAddress((void**)&x1,   g_x1);
    cudaGetSymbolAddress((void**)&hd1,  g_hd1);
    cudaGetSymbolAddress((void**)&hd2,  g_hd2);

    // ---------- encoder: 3 fused gather-GEMMs -> z0 ----------
    { dim3 g(8, 24); enc_gemm<1, 1><<<g, 256>>>(y,  ew0, rw0, eb0, rb0, x0, 256);  }
    { dim3 g(8, 16); enc_gemm<2, 1><<<g, 256>>>(x0, ew1, rw1, eb1, rb1, x1, 1024); }
    { dim3 g(8, 8);  enc_gemm<3, 0><<<g, 256>>>(x1, ew2, rw2, eb2, rb2, zbuf, 768);}

    // ---------- precompute G = fw0 @ fw2, g0 = fw0 @ fb2 ----------
    { dim3 g(8, 8); gemmG_kernel<<<g, 256>>>(fw0, fw2, Gm); }
    g0_kernel<<<2, 256>>>(fw0, fb2, g0);

    // ---------- RK4 ODE: persistent kernel, 8 syncs/step ----------
    const int smem_bytes = (16384 + 16384 + 8192 + 8192 + 4096 + 80) * 4;
    cudaFuncSetAttribute(ode_kernel, cudaFuncAttributeMaxDynamicSharedMemorySize,
                         smem_bytes);
    ode_kernel<<<NBLK, 256, smem_bytes>>>(t, fw0, fb0, fw1, fb1, fw2, fb2,
                                          Gm, g0, zbuf, h1, h2, sbuf);

    // ---------- decoder over all 200 states ----------
    { dim3 g(DECH / 64, TSTEPS * BSZ / 64); dec_gemm<1><<<g, 256>>>(zbuf, dw0, db0, hd1, TSTEPS * BSZ, DECH, LATD); }
    { dim3 g(DECH / 64, TSTEPS * BSZ / 64); dec_gemm<1><<<g, 256>>>(hd1,  dw1, db1, hd2, TSTEPS * BSZ, DECH, DECH); }
    { dim3 g(SIG  / 64, TSTEPS * BSZ / 64); dec_gemm<3><<<g, 256>>>(hd2,  dw2, db2, out, TSTEPS * BSZ, SIG,  DECH); }
}